// round 5
// baseline (speedup 1.0000x reference)
#include <cuda_runtime.h>

#define NB   8
#define NC   256
#define NH   96
#define NW   96
#define HW_  (NH * NW)          // 9216
#define CHW_ (NC * HW_)
#define NTOT (NB * CHW_)
#define TPB  128
#define NBLK (NB * HW_ / TPB)   // 576

// Per channel: 9 float4 quads, quad(yq, xb) = { w[yq][xb], w[yq][xb+1],
//                                              w[yq+1][xb], w[yq+1][xb+1] }
// yq, xb in {0,1,2}. 36 words / channel, 16B-aligned (36*4 = 144 B).
#define QSTRIDE 36

__global__ __launch_bounds__(TPB)
void sdw_kernel(const float* __restrict__ x,
                const float* __restrict__ rot,
                const float* __restrict__ wgt,
                float* __restrict__ out)
{
    __shared__ __align__(16) float wsm[NC * QSTRIDE];

    const int tid = threadIdx.x;
    // Build quads: 256 channels * 9 quads = 2304 quads, 18 per thread.
    for (int i = tid; i < NC * 9; i += TPB) {
        int c = i / 9, q = i % 9;
        int yq = q / 3, xb = q % 3;
        const float* wc = wgt + c * 16;
        float4 v;
        v.x = wc[yq * 4 + xb];
        v.y = wc[yq * 4 + xb + 1];
        v.z = wc[yq * 4 + xb + 4];
        v.w = wc[yq * 4 + xb + 5];
        *reinterpret_cast<float4*>(&wsm[c * QSTRIDE + q * 4]) = v;
    }
    __syncthreads();

    const int blk = blockIdx.x;
    const int b   = blk / (HW_ / TPB);
    const int pix = (blk % (HW_ / TPB)) * TPB + tid;
    const int h = pix / NW, w = pix % NW;

    // Per-tap: 4 combined corner coefficients + one quad word-offset.
    float c00[9], c01[9], c10[9], c11[9];
    int qo[9];

    const float* rbase = rot + (b * 18) * HW_ + pix;
    #pragma unroll
    for (int kh = 0; kh < 3; kh++) {
        #pragma unroll
        for (int kw = 0; kw < 3; kw++) {
            const int t = kh * 3 + kw;
            float ryv = __ldg(rbase + (2 * t) * HW_);
            float rxv = __ldg(rbase + (2 * t + 1) * HW_);
            float py = (kh + 0.5f) * (4.0f / 3.0f) - 0.5f + ryv;
            float px = (kw + 0.5f) * (4.0f / 3.0f) - 0.5f + rxv;
            float fpy = floorf(py), fpx = floorf(px);
            int iy = (int)fpy, ix = (int)fpx;
            float fy = py - fpy, fx = px - fpx;
            // Corner weights, zeroed when that corner lies outside the 4x4 scope.
            float ry0 = (iy >= 0  && iy < 4) ? (1.f - fy) : 0.f;   // row iy
            float ry1 = (iy >= -1 && iy < 3) ? fy         : 0.f;   // row iy+1
            float rx0 = (ix >= 0  && ix < 4) ? (1.f - fx) : 0.f;   // col ix
            float rx1 = (ix >= -1 && ix < 3) ? fx         : 0.f;   // col ix+1
            // Quad base + coefficient remap. Quad covers cols (xb, xb+1),
            // rows (yq, yq+1); remap the valid corner coefs onto quad slots.
            int xb = min(max(ix, 0), 2);
            int dx = ix - xb;                      // -1/0/+1 in-range, else both 0
            float e0 = (dx == 0) ? rx0 : ((dx == -1) ? rx1 : 0.f);
            float e1 = (dx == 0) ? rx1 : ((dx ==  1) ? rx0 : 0.f);
            int yq = min(max(iy, 0), 2);
            int dy = iy - yq;
            float f0 = (dy == 0) ? ry0 : ((dy == -1) ? ry1 : 0.f);
            float f1 = (dy == 0) ? ry1 : ((dy ==  1) ? ry0 : 0.f);
            // Fold the zero-padding of x into the coefficients so inner-loop
            // x loads can be unconditional (loaded value irrelevant when 0).
            int hh = h + kh - 1, ww = w + kw - 1;
            float xval = (hh >= 0 && hh < NH && ww >= 0 && ww < NW) ? 1.f : 0.f;
            f0 *= xval; f1 *= xval;
            c00[t] = f0 * e0; c01[t] = f0 * e1;
            c10[t] = f1 * e0; c11[t] = f1 * e1;
            qo[t] = (yq * 3 + xb) * 4;             // float4-aligned word offset
        }
    }

    const int off0 = b * CHW_ + pix;
    // Only the first and last block can form x addresses outside the buffer
    // (|imm| <= 97); they take the bounds-checked path.
    const bool guard = (blk == 0) || (blk == NBLK - 1);

    if (!guard) {
        const float* xp = x + off0;
        float* op = out + off0;
        int wbase = 0;
        #pragma unroll 2
        for (int c = 0; c < NC; ++c) {
            float acc = 0.f;
            #pragma unroll
            for (int kh = 0; kh < 3; kh++) {
                #pragma unroll
                for (int kw = 0; kw < 3; kw++) {
                    const int t = kh * 3 + kw;
                    float4 q = *reinterpret_cast<const float4*>(&wsm[wbase + qo[t]]);
                    float g = c00[t] * q.x + c01[t] * q.y
                            + c10[t] * q.z + c11[t] * q.w;
                    float xv = __ldg(xp + (kh - 1) * NW + (kw - 1));
                    acc = fmaf(g, xv, acc);
                }
            }
            *op = acc;
            wbase += QSTRIDE; xp += HW_; op += HW_;
        }
    } else {
        float* op = out + off0;
        int off = off0;
        int wbase = 0;
        #pragma unroll 2
        for (int c = 0; c < NC; ++c) {
            float acc = 0.f;
            #pragma unroll
            for (int kh = 0; kh < 3; kh++) {
                #pragma unroll
                for (int kw = 0; kw < 3; kw++) {
                    const int t = kh * 3 + kw;
                    float4 q = *reinterpret_cast<const float4*>(&wsm[wbase + qo[t]]);
                    float g = c00[t] * q.x + c01[t] * q.y
                            + c10[t] * q.z + c11[t] * q.w;
                    int o = off + (kh - 1) * NW + (kw - 1);
                    float xv = (o >= 0 && o < NTOT) ? x[o] : 0.f;
                    acc = fmaf(g, xv, acc);
                }
            }
            *op = acc;
            wbase += QSTRIDE; off += HW_; op += HW_;
        }
    }
}

extern "C" void kernel_launch(void* const* d_in, const int* in_sizes, int n_in,
                              void* d_out, int out_size)
{
    const float* x   = (const float*)d_in[0];
    const float* rot = (const float*)d_in[1];
    const float* wgt = (const float*)d_in[2];
    float* out = (float*)d_out;
    sdw_kernel<<<NBLK, TPB>>>(x, rot, wgt, out);
}